// round 8
// baseline (speedup 1.0000x reference)
#include <cuda_runtime.h>
#include <cuda_bf16.h>
#include <cstdint>

// Problem constants
#define Bb   8
#define Cc   768
#define Nn   256
#define Hh   12
#define Dd   64
#define HN   3072          // Hh*Nn
#define CNsz 196608        // Cc*Nn
#define SCALE 0.125f       // D^-0.5
#define GNT  24            // K tiles of 32 (K = 768)

// Scratch (allocation-free: __device__ globals)
__device__ float g_cp[Bb * CNsz];                 // proj(cross): [B, C, N] fp32
__device__ float g_Mpart[Bb * Hh * 2 * Dd * Dd];  // per-(b,h,nsplit) partial 64x64
__device__ __nv_bfloat16 g_Uhi[Bb * Nn * Cc];     // U hi plane [B, N, C]
__device__ __nv_bfloat16 g_Ulo[Bb * Nn * Cc];     // U lo plane [B, N, C]

// ---- packed f32x2 helpers (for k_mpart) ----
#define FMA_F32X2(d, a, b, c) \
    asm("fma.rn.f32x2 %0, %1, %2, %3;" : "=l"(d) : "l"(a), "l"(b), "l"(c))

static __device__ __forceinline__ unsigned long long splat2(float x) {
    unsigned long long r;
    unsigned u = __float_as_uint(x);
    asm("mov.b64 %0, {%1, %1};" : "=l"(r) : "r"(u));
    return r;
}
static __device__ __forceinline__ float2 unpack2(unsigned long long v) {
    unsigned lo, hi;
    asm("mov.b64 {%0, %1}, %2;" : "=r"(lo), "=r"(hi) : "l"(v));
    return make_float2(__uint_as_float(lo), __uint_as_float(hi));
}

// ---- tensor-core primitives ----
static __device__ __forceinline__ uint32_t smem_u32(const void* p) {
    return (uint32_t)__cvta_generic_to_shared(p);
}

#define LDSM_X4(r0, r1, r2, r3, addr) \
    asm volatile("ldmatrix.sync.aligned.m8n8.x4.shared.b16 {%0,%1,%2,%3}, [%4];" \
        : "=r"(r0), "=r"(r1), "=r"(r2), "=r"(r3) : "r"(addr))

#define LDSM_X4_T(r0, r1, r2, r3, addr) \
    asm volatile("ldmatrix.sync.aligned.m8n8.x4.trans.shared.b16 {%0,%1,%2,%3}, [%4];" \
        : "=r"(r0), "=r"(r1), "=r"(r2), "=r"(r3) : "r"(addr))

#define MMA_BF16(D, a0, a1, a2, a3, b0, b1) \
    asm volatile("mma.sync.aligned.m16n8k16.row.col.f32.bf16.bf16.f32 " \
        "{%0,%1,%2,%3}, {%4,%5,%6,%7}, {%8,%9}, {%0,%1,%2,%3};" \
        : "+f"((D)[0]), "+f"((D)[1]), "+f"((D)[2]), "+f"((D)[3]) \
        : "r"(a0), "r"(a1), "r"(a2), "r"(a3), "r"(b0), "r"(b1))

// Split 8 fp32 -> bf16 hi chunk (16B) + bf16 lo chunk (16B)
static __device__ __forceinline__ void split8(float4 u, float4 v, uint4& hi, uint4& lo) {
    float f[8] = {u.x, u.y, u.z, u.w, v.x, v.y, v.z, v.w};
    uint32_t hw[4], lw[4];
#pragma unroll
    for (int i = 0; i < 4; i++) {
        __nv_bfloat16 h0 = __float2bfloat16(f[2 * i]);
        __nv_bfloat16 h1 = __float2bfloat16(f[2 * i + 1]);
        __nv_bfloat16 l0 = __float2bfloat16(f[2 * i] - __bfloat162float(h0));
        __nv_bfloat16 l1 = __float2bfloat16(f[2 * i + 1] - __bfloat162float(h1));
        __nv_bfloat162 hh(h0, h1), ll(l0, l1);
        hw[i] = *reinterpret_cast<uint32_t*>(&hh);
        lw[i] = *reinterpret_cast<uint32_t*>(&ll);
    }
    hi = make_uint4(hw[0], hw[1], hw[2], hw[3]);
    lo = make_uint4(lw[0], lw[1], lw[2], lw[3]);
}

// ============================================================================
// Kernel 1: cp = W_proj @ cross + b_proj, bf16 3-split tensor core.
// Block 64(o) x 64(n), 128 threads (4 warps of 32x32), BK=32, double-buffered.
// Grid (32, 12) = 384 blocks; 4 blocks/SM target.
// ============================================================================
__global__ __launch_bounds__(128, 4) void k_proj_mma(
    const float* __restrict__ W, const float* __restrict__ cross,
    const float* __restrict__ bias)
{
    __shared__ uint4 As4[2][64][8];   // [buf][m][chunk 0-3 hi / 4-7 lo], XOR swizzle
    __shared__ uint4 Bs4[2][64][8];   // [buf][k 0-31 hi / 32-63 lo][n chunk]
    const int tid = threadIdx.x;
    const int wid = tid >> 5, lane = tid & 31;
    const int b = blockIdx.x >> 2;
    const int noff = (blockIdx.x & 3) * 64;
    const int otile = blockIdx.y * 64;

    const int wm = (wid >> 1) * 32;   // 0,32
    const int wn = (wid & 1) * 32;    // 0,32
    const int l7 = lane & 7, l15 = lane & 15, lsel = lane >> 4;
    const int g = lane >> 2, tc = lane & 3;

    // A staging: row = tid>>1 (0..63), k-half = tid&1 (chunks 2*(tid&1)..+1)
    const int arow = tid >> 1, ac2 = (tid & 1) * 2;
    const int am7 = arow & 7;
    // B staging: k-row = tid>>2 (0..31), n chunk pair = (tid&3)*2
    const int bkrow = tid >> 2, bc2 = (tid & 3) * 2;
    const int bk7 = bkrow & 7;

    const float* Agp = W + (size_t)(otile + arow) * Cc + (tid & 1) * 16;
    const float* Bgp = cross + (size_t)b * CNsz + (size_t)bkrow * Nn + noff + bc2 * 8;

    const uint32_t as_base = smem_u32(&As4[0][0][0]);
    const uint32_t bs_base = smem_u32(&Bs4[0][0][0]);

    float acc[2][4][4];
#pragma unroll
    for (int i = 0; i < 2; i++)
#pragma unroll
        for (int j = 0; j < 4; j++)
#pragma unroll
            for (int e = 0; e < 4; e++) acc[i][j][e] = 0.f;

    float4 av[4], bv[4];
#pragma unroll
    for (int i = 0; i < 4; i++) {
        av[i] = *(const float4*)(Agp + i * 4);
        bv[i] = *(const float4*)(Bgp + i * 4);
    }

    {
        uint4 h, l;
        split8(av[0], av[1], h, l);
        As4[0][arow][(ac2 + 0) ^ am7] = h;
        As4[0][arow][(ac2 + 4) ^ am7] = l;
        split8(av[2], av[3], h, l);
        As4[0][arow][(ac2 + 1) ^ am7] = h;
        As4[0][arow][(ac2 + 5) ^ am7] = l;
        split8(bv[0], bv[1], h, l);
        Bs4[0][bkrow][(bc2 + 0) ^ bk7] = h;
        Bs4[0][bkrow + 32][(bc2 + 0) ^ bk7] = l;
        split8(bv[2], bv[3], h, l);
        Bs4[0][bkrow][(bc2 + 1) ^ bk7] = h;
        Bs4[0][bkrow + 32][(bc2 + 1) ^ bk7] = l;
    }
    __syncthreads();

    for (int kt = 0; kt < GNT; kt++) {
        const int cur = kt & 1;
        if (kt + 1 < GNT) {
            Agp += 32;
            Bgp += (size_t)32 * Nn;
#pragma unroll
            for (int i = 0; i < 4; i++) {
                av[i] = *(const float4*)(Agp + i * 4);
                bv[i] = *(const float4*)(Bgp + i * 4);
            }
        }

        const uint32_t asb = as_base + (uint32_t)cur * 8192;
        const uint32_t bsb = bs_base + (uint32_t)cur * 8192;
#pragma unroll
        for (int ks = 0; ks < 2; ks++) {
            const int k0 = ks * 16;
            uint32_t ah[2][4], al[2][4];
#pragma unroll
            for (int mf = 0; mf < 2; mf++) {
                const uint32_t rbase = asb + (uint32_t)(wm + mf * 16 + l15) * 128;
                const int ch = ((k0 >> 3) + lsel) ^ l7;
                const int cl = ((k0 >> 3) + lsel + 4) ^ l7;
                LDSM_X4(ah[mf][0], ah[mf][1], ah[mf][2], ah[mf][3], rbase + ch * 16);
                LDSM_X4(al[mf][0], al[mf][1], al[mf][2], al[mf][3], rbase + cl * 16);
            }
#pragma unroll
            for (int np = 0; np < 2; np++) {
                const int c = (wn >> 3) + np * 2 + lsel;
                const int p = c ^ l7;
                const uint32_t rb = bsb + (uint32_t)(k0 + l15) * 128 + p * 16;
                uint32_t bh[4], bl[4];
                LDSM_X4_T(bh[0], bh[1], bh[2], bh[3], rb);
                LDSM_X4_T(bl[0], bl[1], bl[2], bl[3], rb + 32 * 128);
#pragma unroll
                for (int mf = 0; mf < 2; mf++) {
                    MMA_BF16(acc[mf][2 * np], ah[mf][0], ah[mf][1], ah[mf][2], ah[mf][3], bh[0], bh[1]);
                    MMA_BF16(acc[mf][2 * np], al[mf][0], al[mf][1], al[mf][2], al[mf][3], bh[0], bh[1]);
                    MMA_BF16(acc[mf][2 * np], ah[mf][0], ah[mf][1], ah[mf][2], ah[mf][3], bl[0], bl[1]);
                    MMA_BF16(acc[mf][2 * np + 1], ah[mf][0], ah[mf][1], ah[mf][2], ah[mf][3], bh[2], bh[3]);
                    MMA_BF16(acc[mf][2 * np + 1], al[mf][0], al[mf][1], al[mf][2], al[mf][3], bh[2], bh[3]);
                    MMA_BF16(acc[mf][2 * np + 1], ah[mf][0], ah[mf][1], ah[mf][2], ah[mf][3], bl[2], bl[3]);
                }
            }
        }

        if (kt + 1 < GNT) {
            const int nxt = cur ^ 1;
            uint4 h, l;
            split8(av[0], av[1], h, l);
            As4[nxt][arow][(ac2 + 0) ^ am7] = h;
            As4[nxt][arow][(ac2 + 4) ^ am7] = l;
            split8(av[2], av[3], h, l);
            As4[nxt][arow][(ac2 + 1) ^ am7] = h;
            As4[nxt][arow][(ac2 + 5) ^ am7] = l;
            split8(bv[0], bv[1], h, l);
            Bs4[nxt][bkrow][(bc2 + 0) ^ bk7] = h;
            Bs4[nxt][bkrow + 32][(bc2 + 0) ^ bk7] = l;
            split8(bv[2], bv[3], h, l);
            Bs4[nxt][bkrow][(bc2 + 1) ^ bk7] = h;
            Bs4[nxt][bkrow + 32][(bc2 + 1) ^ bk7] = l;
            __syncthreads();
        }
    }

    // Epilogue: cp[o][n] + bias
#pragma unroll
    for (int mf = 0; mf < 2; mf++) {
        const int o = otile + wm + mf * 16 + g;
        const float b0v = bias[o], b1v = bias[o + 8];
        float* base = g_cp + (size_t)b * CNsz + (size_t)o * Nn + noff + wn + tc * 2;
#pragma unroll
        for (int nf = 0; nf < 4; nf++) {
            *(float2*)(base + nf * 8) =
                make_float2(acc[mf][nf][0] + b0v, acc[mf][nf][1] + b0v);
            *(float2*)(base + nf * 8 + 8 * Nn) =
                make_float2(acc[mf][nf][2] + b1v, acc[mf][nf][3] + b1v);
        }
    }
}

// ============================================================================
// Kernel 2: Mpart[b,h,s][d,d'] = sum_{n in half s} cp[b,d*H+h,n]*cross[b,d'*H+h,n]
// Grid (12, 8, 2); f32x2 4x4 micro, K=128 per block.
// ============================================================================
__global__ __launch_bounds__(256) void k_mpart(const float* __restrict__ cross)
{
    __shared__ float As[16][64];
    __shared__ float Bs[16][64];
    const int h = blockIdx.x;
    const int b = blockIdx.y;
    const int s = blockIdx.z;
    const int tid = threadIdx.x;
    const int r = tid >> 4, c = tid & 15;
    const int lr = tid >> 2, lk = (tid & 3) * 4;

    const float* Ab = g_cp + (size_t)b * CNsz + h * Nn + s * 128;
    const float* Bp = cross + (size_t)b * CNsz + h * Nn + s * 128;

    unsigned long long acc[4][2];
#pragma unroll
    for (int i = 0; i < 4; i++) { acc[i][0] = 0ull; acc[i][1] = 0ull; }

    for (int k0 = 0; k0 < 128; k0 += 16) {
        float4 av = *(const float4*)(Ab + (size_t)lr * HN + k0 + lk);
        float4 bv = *(const float4*)(Bp + (size_t)lr * HN + k0 + lk);
        __syncthreads();
        As[lk + 0][lr] = av.x; As[lk + 1][lr] = av.y;
        As[lk + 2][lr] = av.z; As[lk + 3][lr] = av.w;
        Bs[lk + 0][lr] = bv.x; Bs[lk + 1][lr] = bv.y;
        Bs[lk + 2][lr] = bv.z; Bs[lk + 3][lr] = bv.w;
        __syncthreads();
#pragma unroll
        for (int k = 0; k < 16; k++) {
            float4 ar = *(const float4*)&As[k][r * 4];
            ulonglong2 bp = *(const ulonglong2*)&Bs[k][c * 4];
            unsigned long long sv;
            sv = splat2(ar.x);
            FMA_F32X2(acc[0][0], sv, bp.x, acc[0][0]);
            FMA_F32X2(acc[0][1], sv, bp.y, acc[0][1]);
            sv = splat2(ar.y);
            FMA_F32X2(acc[1][0], sv, bp.x, acc[1][0]);
            FMA_F32X2(acc[1][1], sv, bp.y, acc[1][1]);
            sv = splat2(ar.z);
            FMA_F32X2(acc[2][0], sv, bp.x, acc[2][0]);
            FMA_F32X2(acc[2][1], sv, bp.y, acc[2][1]);
            sv = splat2(ar.w);
            FMA_F32X2(acc[3][0], sv, bp.x, acc[3][0]);
            FMA_F32X2(acc[3][1], sv, bp.y, acc[3][1]);
        }
    }

    float* mp = g_Mpart + (((size_t)b * Hh + h) * 2 + s) * 4096;
#pragma unroll
    for (int i = 0; i < 4; i++) {
        float2 lo = unpack2(acc[i][0]);
        float2 hi = unpack2(acc[i][1]);
        *(float4*)(mp + (size_t)(r * 4 + i) * 64 + c * 4) =
            make_float4(lo.x, lo.y, hi.x, hi.y);
    }
}

// ============================================================================
// Kernel 3: U rows = scale * x-row(m) . M[b]; fused (h,s)-reduction of Mpart.
// Grid (96, 4); emits bf16 hi/lo planes for the deproj tensor-core GEMM.
// ============================================================================
__global__ __launch_bounds__(256) void k_out(const float* __restrict__ x_ori)
{
    __shared__ float Ms[64][16];
    const int b = blockIdx.x / Hh;
    const int hp = blockIdx.x % Hh;
    const int q = blockIdx.y;        // d' quarter
    const int tid = threadIdx.x;

    for (int idx = tid; idx < 1024; idx += 256) {
        const int d = idx >> 4, c = idx & 15;
        const float* mp = g_Mpart + ((size_t)b * Hh * 2) * 4096 + d * 64 + q * 16 + c;
        float sacc = 0.f;
#pragma unroll
        for (int hs = 0; hs < Hh * 2; hs++) sacc += mp[(size_t)hs * 4096];
        Ms[d][c] = sacc;
    }
    __syncthreads();

    const float* xb = x_ori + (size_t)b * CNsz + hp * Nn + tid;

    float4 acc[4];
#pragma unroll
    for (int e = 0; e < 4; e++) acc[e] = make_float4(0.f, 0.f, 0.f, 0.f);

    for (int d0 = 0; d0 < 64; d0 += 8) {
        float xr[8];
#pragma unroll
        for (int i = 0; i < 8; i++) xr[i] = xb[(size_t)(d0 + i) * HN];
#pragma unroll
        for (int i = 0; i < 8; i++) {
            const float4* Mr = (const float4*)&Ms[d0 + i][0];
            const float xv = xr[i];
#pragma unroll
            for (int e = 0; e < 4; e++) {
                float4 mv = Mr[e];
                acc[e].x += xv * mv.x;
                acc[e].y += xv * mv.y;
                acc[e].z += xv * mv.z;
                acc[e].w += xv * mv.w;
            }
        }
    }

    const int m = hp * Nn + tid;
    const int nf = m / Hh;
    const int hf = m - nf * Hh;
    const size_t off = ((size_t)b * Nn + nf) * Cc + hf * Dd + q * 16;

    float v[16];
    *(float4*)&v[0] = acc[0]; *(float4*)&v[4] = acc[1];
    *(float4*)&v[8] = acc[2]; *(float4*)&v[12] = acc[3];
    uint32_t hw[8], lw[8];
#pragma unroll
    for (int i = 0; i < 8; i++) {
        float f0 = v[2 * i] * SCALE, f1 = v[2 * i + 1] * SCALE;
        __nv_bfloat16 h0 = __float2bfloat16(f0);
        __nv_bfloat16 h1 = __float2bfloat16(f1);
        __nv_bfloat16 l0 = __float2bfloat16(f0 - __bfloat162float(h0));
        __nv_bfloat16 l1 = __float2bfloat16(f1 - __bfloat162float(h1));
        __nv_bfloat162 hh(h0, h1), ll(l0, l1);
        hw[i] = *reinterpret_cast<uint32_t*>(&hh);
        lw[i] = *reinterpret_cast<uint32_t*>(&ll);
    }
    *(uint4*)(g_Uhi + off)     = make_uint4(hw[0], hw[1], hw[2], hw[3]);
    *(uint4*)(g_Uhi + off + 8) = make_uint4(hw[4], hw[5], hw[6], hw[7]);
    *(uint4*)(g_Ulo + off)     = make_uint4(lw[0], lw[1], lw[2], lw[3]);
    *(uint4*)(g_Ulo + off + 8) = make_uint4(lw[4], lw[5], lw[6], lw[7]);
}

// ============================================================================
// Kernel 4: out = x_ori + b_dep + U @ W_dep^T, bf16 3-split tensor core.
// Block 64(o) x 64(n), 128 threads, double-buffered; B pre-split by k_out.
// Grid (32, 12).
// ============================================================================
__global__ __launch_bounds__(128, 4) void k_deproj_mma(
    const float* __restrict__ Wdep, const float* __restrict__ bdep,
    const float* __restrict__ x_ori, float* __restrict__ out)
{
    __shared__ uint4 As4[2][64][8];   // [buf][o][chunk hi 0-3 / lo 4-7]
    __shared__ uint4 Bs4[2][64][8];   // [buf][n][chunk hi 0-3 / lo 4-7]
    const int tid = threadIdx.x;
    const int wid = tid >> 5, lane = tid & 31;
    const int b = blockIdx.x >> 2;
    const int noff = (blockIdx.x & 3) * 64;
    const int otile = blockIdx.y * 64;

    const int wm = (wid >> 1) * 32;
    const int wn = (wid & 1) * 32;
    const int l7 = lane & 7, l15 = lane & 15, lsel = lane >> 4;
    const int ksel = (lane >> 3) & 1;
    const int rowNl = (lane & 7) + (lsel << 3);
    const int g = lane >> 2, tc = lane & 3;

    const int arow = tid >> 1, ac2 = (tid & 1) * 2;
    const int am7 = arow & 7;
    const int brow = tid >> 1, bch = (tid & 1) * 2;   // B: n-row, k chunk pair
    const int bn7 = brow & 7;

    const float* Agp = Wdep + (size_t)(otile + arow) * Cc + (tid & 1) * 16;
    const __nv_bfloat16* Uhp = g_Uhi + ((size_t)b * Nn + noff + brow) * Cc + (tid & 1) * 16;
    const __nv_bfloat16* Ulp = g_Ulo + ((size_t)b * Nn + noff + brow) * Cc + (tid & 1) * 16;

    const uint32_t as_base = smem_u32(&As4[0][0][0]);
    const uint32_t bs_base = smem_u32(&Bs4[0][0][0]);

    float acc[2][4][4];
#pragma unroll
    for (int i = 0; i < 2; i++)
#pragma unroll
        for (int j = 0; j < 4; j++)
#pragma unroll
            for (int e = 0; e < 4; e++) acc[i][j][e] = 0.f;

    float4 av[4];
    uint4 uh0, uh1, ul0, ul1;
#pragma unroll
    for (int i = 0; i < 4; i++) av[i] = *(const float4*)(Agp + i * 4);
    uh0 = *(const uint4*)(Uhp);
    uh1 = *(const uint4*)(Uhp + 8);
    ul0 = *(const uint4*)(Ulp);
    ul1 = *(const uint4*)(Ulp + 8);

    {
        uint4 h, l;
        split8(av[0], av[1], h, l);
        As4[0][arow][(ac2 + 0) ^ am7] = h;
        As4[0][arow][(ac2 + 4) ^ am7] = l;
        split8(av[2], av[3], h, l);
        As4[0][arow][(ac2 + 1) ^ am7] = h;
        As4[0][arow][(ac2 + 5) ^ am7] = l;
        Bs4[0][brow][(bch + 0) ^ bn7] = uh0;
        Bs4[0][brow][(bch + 1) ^ bn7] = uh1;
        Bs4[0][brow][(bch + 4) ^ bn7] = ul0;
        Bs4[0][brow][(bch + 5) ^ bn7] = ul1;
    }
    __syncthreads();

    for (int kt = 0; kt < GNT; kt++) {
        const int cur = kt & 1;
        if (kt + 1 < GNT) {
            Agp += 32; Uhp += 32; Ulp += 32;
#pragma unroll
            for (int i = 0; i < 4; i++) av[i] = *(const float4*)(Agp + i * 4);
            uh0 = *(const uint4*)(Uhp);
            uh1 = *(const uint4*)(Uhp + 8);
            ul0 = *(const uint4*)(Ulp);
            ul1 = *(const uint4*)(Ulp + 8);
        }

        const uint32_t asb = as_base + (uint32_t)cur * 8192;
        const uint32_t bsb = bs_base + (uint32_t)cur * 8192;
#pragma unroll
        for (int ks = 0; ks < 2; ks++) {
            const int k0 = ks * 16;
            uint32_t ah[2][4], al[2][4];
#pragma unroll
            for (int mf = 0; mf < 2; mf++) {
                const uint32_t rbase = asb + (uint32_t)(wm + mf * 16 + l15) * 128;
                const int ch = ((k0 >> 3) + lsel) ^ l7;
                const int cl = ((k0 >> 3) + lsel + 4) ^ l7;
                LDSM_X4(ah[mf][0], ah[mf][1], ah[mf][2], ah[mf][3], rbase + ch * 16);
                LDSM_X4(al[mf][0], al[mf][1], al[mf][2], al[mf][3], rbase + cl * 16);
            }
#pragma unroll
            for (int np = 0; np < 2; np++) {
                const int rowN = wn + np * 16 + rowNl;
                const int ch = ((k0 >> 3) + ksel) ^ l7;
                const int cl = ((k0 >> 3) + ksel + 4) ^ l7;
                const uint32_t rb = bsb + (uint32_t)rowN * 128;
                uint32_t bh[4], bl[4];
                LDSM_X4(bh[0], bh[1], bh[2], bh[3], rb + ch * 16);
                LDSM_X4(bl[0], bl[1], bl[2], bl[3], rb + cl * 16);
#pragma unroll
                for (int mf = 0; mf < 2; mf++) {
                    MMA_BF16(acc[mf][2 * np], ah[mf][0], ah[mf][1], ah[mf][2], ah[mf][3], bh[0], bh[1]);
                    MMA_BF16(acc[mf][2 * np], al[mf][0], al[mf][1], al[mf][2], al[mf][3], bh[0], bh[1]);
                    MMA_BF16(acc[mf][2 * np], ah[mf][0], ah[mf][1], ah[mf][2], ah[mf][3], bl[0], bl[1]);
                    MMA_BF16(acc[mf][2 * np + 1], ah[mf][0], ah[mf][1], ah[mf][2], ah[mf][3], bh[2], bh[3]);
                    MMA_BF16(acc[mf][2 * np + 1], al[mf][0], al[mf][1], al[mf][2], al[mf][3], bh[2], bh[3]);
                    MMA_BF16(acc[mf][2 * np + 1], ah[mf][0], ah[mf][1], ah[mf][2], ah[mf][3], bl[2], bl[3]);
                }
            }
        }

        if (kt + 1 < GNT) {
            const int nxt = cur ^ 1;
            uint4 h, l;
            split8(av[0], av[1], h, l);
            As4[nxt][arow][(ac2 + 0) ^ am7] = h;
            As4[nxt][arow][(ac2 + 4) ^ am7] = l;
            split8(av[2], av[3], h, l);
            As4[nxt][arow][(ac2 + 1) ^ am7] = h;
            As4[nxt][arow][(ac2 + 5) ^ am7] = l;
            Bs4[nxt][brow][(bch + 0) ^ bn7] = uh0;
            Bs4[nxt][brow][(bch + 1) ^ bn7] = uh1;
            Bs4[nxt][brow][(bch + 4) ^ bn7] = ul0;
            Bs4[nxt][brow][(bch + 5) ^ bn7] = ul1;
            __syncthreads();
        }
    }

    // Epilogue: + bias + skip
#pragma unroll
    for (int mf = 0; mf < 2; mf++) {
        const int o = otile + wm + mf * 16 + g;
        const float b0v = bdep[o], b1v = bdep[o + 8];
        const size_t base = (size_t)b * CNsz + (size_t)o * Nn + noff + wn + tc * 2;
#pragma unroll
        for (int nf = 0; nf < 4; nf++) {
            const size_t i0 = base + nf * 8;
            float2 x0 = *(const float2*)(x_ori + i0);
            float2 x1 = *(const float2*)(x_ori + i0 + 8 * Nn);
            *(float2*)(out + i0) =
                make_float2(acc[mf][nf][0] + b0v + x0.x, acc[mf][nf][1] + b0v + x0.y);
            *(float2*)(out + i0 + 8 * Nn) =
                make_float2(acc[mf][nf][2] + b1v + x1.x, acc[mf][nf][3] + b1v + x1.y);
        }
    }
}

// ============================================================================
// Launch
// ============================================================================
extern "C" void kernel_launch(void* const* d_in, const int* in_sizes, int n_in,
                              void* d_out, int out_size)
{
    (void)in_sizes; (void)n_in; (void)out_size;
    const float* x_ori  = (const float*)d_in[0];
    const float* cross  = (const float*)d_in[1];
    const float* W_proj = (const float*)d_in[2];
    const float* b_proj = (const float*)d_in[3];
    const float* W_dep  = (const float*)d_in[4];
    const float* b_dep  = (const float*)d_in[5];
    float* out = (float*)d_out;

    k_proj_mma<<<dim3(32, 12), 128>>>(W_proj, cross, b_proj);
    k_mpart<<<dim3(Hh, Bb, 2), 256>>>(cross);
    k_out<<<dim3(Bb * Hh, 4), 256>>>(x_ori);
    k_deproj_mma<<<dim3(32, 12), 128>>>(W_dep, b_dep, x_ori, out);
}